// round 14
// baseline (speedup 1.0000x reference)
#include <cuda_runtime.h>

// Fan-beam CT forward projector — two-phase bin-pair gather (R12 base):
//  setup precomputes per-(view,pair) wedge coeffs (margins baked) + window,
//  main kernel: warp per 2 bins, slim 3xfloat4 prologue, unroll-5 walk.
constexpr int   R_      = 384;
constexpr int   C_      = 384;
constexpr int   NCOLS_  = 768;
constexpr int   V_      = 256;
constexpr float DR_     = 1.0f;
constexpr float DC_     = 1.0f;
constexpr float DSPACE_ = 1.5f;

constexpr int WARPS_PER_BLOCK = 4;
constexpr int NPAIRS = NCOLS_ / 2;     // 384
constexpr int NWORK  = V_ * NPAIRS;    // 98304

// per-(view,pair): [0]=(q0,qs,qp,b0) [1]=(bs,bp,alo-.01,blo) [2]=(ahi+.01,bhi,w0i,pack(w1i|flag))
__device__ float4 g_pre[NWORK * 3];

__device__ __forceinline__ void drive_window(float ahi, float bhi,
                                             float alo, float blo,
                                             int& w0, int& w1)
{
    float f0 = 0.0f, f1 = 383.0f;
    const float eps = 1e-12f;
    if (bhi > eps)        f0 = fmaxf(f0, __fdividef(-0.01f - ahi, bhi) - 1.0f);
    else if (bhi < -eps)  f1 = fminf(f1, __fdividef(-0.01f - ahi, bhi) + 1.0f);
    else if (ahi < -0.01f) { w0 = 1; w1 = 0; return; }
    const float L = 383.01f;
    if (blo > eps)        f1 = fminf(f1, __fdividef(L - alo, blo) + 1.0f);
    else if (blo < -eps)  f0 = fmaxf(f0, __fdividef(L - alo, blo) - 1.0f);
    else if (alo > L)     { w0 = 1; w1 = 0; return; }
    w0 = max(0, __float2int_ru(f0));
    w1 = min(383, __float2int_rd(f1));
}

__global__ void setup_kernel(const float* __restrict__ src_g,
                             const float* __restrict__ detc_g,
                             const float* __restrict__ u_g,
                             const float* __restrict__ center_g,
                             const float* __restrict__ cdir_g)
{
    const int idx = blockIdx.x * blockDim.x + threadIdx.x;
    if (idx >= NWORK) return;
    const int v    = idx / NPAIRS;
    const int pair = idx - v * NPAIRS;
    const int ib   = pair * 2;

    const float sx  = src_g [2*v+0], sy  = src_g [2*v+1];
    const float dcx = detc_g[2*v+0], dcy = detc_g[2*v+1];
    const float ux  = u_g  [2*v+0], uy  = u_g  [2*v+1];
    const float nx  = -uy,          ny  = ux;
    const float cx  = center_g[0],  cy  = center_g[1];
    const float colx = cdir_g[0],   coly = cdir_g[1];
    const float rowx = -coly,       rowy = colx;

    const float vzx = cx - 0.5f*(R_-1)*DR_*rowx - 0.5f*(C_-1)*DC_*colx;
    const float vzy = cy - 0.5f*(R_-1)*DR_*rowy - 0.5f*(C_-1)*DC_*coly;

    const float src_d = sx*nx + sy*ny;
    const float su    = sx*ux + sy*uy;
    const float K     = (dcx*nx + dcy*ny) - src_d;
    const float h     = 0.5f*(NCOLS_-1)*DSPACE_;
    const float dzx   = dcx - h*ux, dzy = dcy - h*uy;
    const float A     = su - (dzx*ux + dzy*uy);

    const float bn0 = vzx*nx + vzy*ny - src_d;
    const float dnr = DR_*(rowx*nx + rowy*ny);
    const float dnc = DC_*(colx*nx + coly*ny);
    const float bu0 = vzx*ux + vzy*uy - su;
    const float dur = DR_*(rowx*ux + rowy*uy);
    const float duc = DC_*(colx*ux + coly*uy);

    const float den_c = bn0 + 0.5f*(R_-1)*dnr + 0.5f*(C_-1)*dnc;
    const float sig   = (den_c > 0.0f) ? 1.0f : -1.0f;
    const bool  tok   = (sig * K) > 0.0f;

    const float E  = A - (float)ib * DSPACE_;
    const float q0 = sig * (E*bn0 + K*bu0);
    const float qr = sig * (E*dnr + K*dur);
    const float qc = sig * (E*dnc + K*duc);
    const float b0 = sig * DSPACE_ * bn0;
    const float br = sig * DSPACE_ * dnr;
    const float bc = sig * DSPACE_ * dnc;

    const float ic_f = (float)ib + 0.5f;
    const float bxp = dzx + ic_f*DSPACE_*ux - sx;
    const float byp = dzy + ic_f*DSPACE_*uy - sy;
    const float dc_comp = bxp*colx + byp*coly;
    const float dr_comp = bxp*rowx + byp*rowy;
    const bool  drive_c = fabsf(dc_comp) >= fabsf(dr_comp);

    const float qs = drive_c ? qc : qr;
    const float qp = drive_c ? qr : qc;
    const float bs = drive_c ? bc : br;
    const float bp = drive_c ? br : bc;

    // pair wedge lines: Q + B = 0 (col = ib-1), Q - 2B = 0 (col = ib+2)
    const float gm  = qp + bp;
    const float gp2 = qp - 2.0f*bp;
    const float am  = __fdividef(-(q0 + b0),      gm);
    const float bm  = __fdividef(-(qs + bs),      gm);
    const float ap  = __fdividef(-(q0 - 2.0f*b0), gp2);
    const float bp3 = __fdividef(-(qs - 2.0f*bs), gp2);
    float alo, blo, ahi, bhi;
    if (fmaf(191.5f, bm, am) <= fmaf(191.5f, bp3, ap)) {
        alo = am; blo = bm; ahi = ap; bhi = bp3;
    } else {
        alo = ap; blo = bp3; ahi = am; bhi = bm;
    }

    int w0i, w1i;
    if (tok) drive_window(ahi, bhi, alo, blo, w0i, w1i);
    else     { w0i = 1; w1i = 0; }

    const int packed = w1i | (drive_c ? (1 << 16) : 0);

    float4* o = g_pre + idx * 3;
    o[0] = make_float4(q0, qs, qp, b0);
    o[1] = make_float4(bs, bp, alo - 0.01f, blo);     // margin baked
    o[2] = make_float4(ahi + 0.01f, bhi,              // margin baked
                       __int_as_float(w0i), __int_as_float(packed));
}

// Walk driving coordinate s (lanes strided by 32), perp coord p with
// compile-time stride PSTR; SROW is the complementary stride.
template<int PSTR, int SROW>
__device__ __forceinline__ void walk(const float* __restrict__ img,
                                     int lane, int w0i, int w1i,
                                     float q0, float qs, float qp,
                                     float b0, float bs, float bp,
                                     float alo_m, float blo,
                                     float ahi_m, float bhi,
                                     float& acc0, float& acc1)
{
    const float* srow = img + (w0i + lane) * SROW;   // advances by 32*SROW
    for (int s = w0i + lane; s <= w1i; s += 32, srow += 32 * SROW) {
        const float sf  = (float)s;
        const float plo = fmaxf(fmaf(sf, blo, alo_m), 0.0f);
        const float phi = fminf(fmaf(sf, bhi, ahi_m), 383.0f);
        const int p0 = __float2int_ru(plo);
        const int n  = __float2int_rd(phi) - p0;
        if (n >= 0) {
            const float pf0 = (float)p0;
            const float Qb  = fmaf(pf0, qp, fmaf(sf, qs, q0));
            const float Bb  = fmaf(pf0, bp, fmaf(sf, bs, b0));
            const float* p  = srow + p0 * PSTR;
            #pragma unroll
            for (int k = 0; k < 5; ++k) {
                if (k <= n) {
                    const float Qp = fmaf((float)k, qp, Qb);
                    const float Bp = fmaf((float)k, bp, Bb);
                    const float rb = __fdividef(1.0f, Bp);
                    const float val = __ldg(p + k*PSTR);
                    const float wA = fmaf(-fabsf(Qp), rb, 1.0f);
                    const float wB = fmaf(-fabsf(Qp - Bp), rb, 1.0f);
                    acc0 = fmaf(fmaxf(wA, 0.0f), val, acc0);
                    acc1 = fmaf(fmaxf(wB, 0.0f), val, acc1);
                }
            }
            for (int k = 5; k <= n; ++k) {          // cold tail (safety)
                const float Qp = fmaf((float)k, qp, Qb);
                const float Bp = fmaf((float)k, bp, Bb);
                const float rb = __fdividef(1.0f, Bp);
                const float val = __ldg(p + k*PSTR);
                const float wA = fmaf(-fabsf(Qp), rb, 1.0f);
                const float wB = fmaf(-fabsf(Qp - Bp), rb, 1.0f);
                acc0 = fmaf(fmaxf(wA, 0.0f), val, acc0);
                acc1 = fmaf(fmaxf(wB, 0.0f), val, acc1);
            }
        }
    }
}

__global__ __launch_bounds__(32 * WARPS_PER_BLOCK, 12)
void fanbeam_fp_kernel(const float* __restrict__ img,
                       float* __restrict__ sino)
{
    const int v    = blockIdx.y;
    const int warp = threadIdx.x >> 5;
    const int lane = threadIdx.x & 31;
    const int pair = blockIdx.x * WARPS_PER_BLOCK + warp;   // adjacent pairs
    const int ib   = pair * 2;

    const float4* pp = g_pre + (v * NPAIRS + pair) * 3;
    const float4 A0 = __ldg(pp + 0);
    const float4 A1 = __ldg(pp + 1);
    const float4 A2 = __ldg(pp + 2);

    const float q0 = A0.x, qs = A0.y, qp = A0.z, b0 = A0.w;
    const float bs = A1.x, bp = A1.y, alo_m = A1.z, blo = A1.w;
    const float ahi_m = A2.x, bhi = A2.y;
    const int   w0i    = __float_as_int(A2.z);
    const int   packed = __float_as_int(A2.w);
    const int   w1i    = packed & 0xFFFF;
    const bool  drive_c = (packed >> 16) != 0;

    float acc0 = 0.0f, acc1 = 0.0f;

    if (w0i <= w1i) {
        if (drive_c)
            walk<C_, 1>(img, lane, w0i, w1i, q0, qs, qp, b0, bs, bp,
                        alo_m, blo, ahi_m, bhi, acc0, acc1);
        else
            walk<1, C_>(img, lane, w0i, w1i, q0, qs, qp, b0, bs, bp,
                        alo_m, blo, ahi_m, bhi, acc0, acc1);
    }

    #pragma unroll
    for (int off = 16; off > 0; off >>= 1) {
        acc0 += __shfl_xor_sync(0xffffffffu, acc0, off);
        acc1 += __shfl_xor_sync(0xffffffffu, acc1, off);
    }

    if (lane == 0) {
        sino[v*NCOLS_ + ib]     = acc0;
        sino[v*NCOLS_ + ib + 1] = acc1;
    }
}

extern "C" void kernel_launch(void* const* d_in, const int* in_sizes, int n_in,
                              void* d_out, int out_size)
{
    const float* img    = (const float*)d_in[0];
    const float* src    = (const float*)d_in[1];
    const float* detc   = (const float*)d_in[2];
    const float* u      = (const float*)d_in[3];
    const float* center = (const float*)d_in[4];
    const float* cdir   = (const float*)d_in[5];
    float* sino = (float*)d_out;

    setup_kernel<<<(NWORK + 255) / 256, 256>>>(src, detc, u, center, cdir);

    dim3 grid(NPAIRS / WARPS_PER_BLOCK, V_);
    dim3 block(32 * WARPS_PER_BLOCK);
    fanbeam_fp_kernel<<<grid, block>>>(img, sino);
}

// round 15
// speedup vs baseline: 3.3684x; 3.3684x over previous
#include <cuda_runtime.h>

// Fan-beam CT forward projector — two-phase bin-pair gather:
//  setup precomputes per-(view,pair) wedge coeffs (margins baked) + window,
//  main kernel: warp per 2 bins, slim 3xfloat4 prologue, unroll-5 walk.
constexpr int   R_      = 384;
constexpr int   C_      = 384;
constexpr int   NCOLS_  = 768;
constexpr int   V_      = 256;
constexpr float DR_     = 1.0f;
constexpr float DC_     = 1.0f;
constexpr float DSPACE_ = 1.5f;

constexpr int WARPS_PER_BLOCK = 4;
constexpr int NPAIRS = NCOLS_ / 2;     // 384
constexpr int NWORK  = V_ * NPAIRS;    // 98304

// per-(view,pair): [0]=(q0,qs,qp,b0) [1]=(bs,bp,alo-.01,blo) [2]=(ahi+.01,bhi,w0i,pack(w1i|flag))
__device__ float4 g_pre[NWORK * 3];

__device__ __forceinline__ void drive_window(float ahi, float bhi,
                                             float alo, float blo,
                                             int& w0, int& w1)
{
    float f0 = 0.0f, f1 = 383.0f;
    const float eps = 1e-12f;
    if (bhi > eps)        f0 = fmaxf(f0, __fdividef(-0.01f - ahi, bhi) - 1.0f);
    else if (bhi < -eps)  f1 = fminf(f1, __fdividef(-0.01f - ahi, bhi) + 1.0f);
    else if (ahi < -0.01f) { w0 = 1; w1 = 0; return; }
    const float L = 383.01f;
    if (blo > eps)        f1 = fminf(f1, __fdividef(L - alo, blo) + 1.0f);
    else if (blo < -eps)  f0 = fmaxf(f0, __fdividef(L - alo, blo) - 1.0f);
    else if (alo > L)     { w0 = 1; w1 = 0; return; }
    w0 = max(0, __float2int_ru(f0));
    w1 = min(383, __float2int_rd(f1));
}

__global__ void setup_kernel(const float* __restrict__ src_g,
                             const float* __restrict__ detc_g,
                             const float* __restrict__ u_g,
                             const float* __restrict__ center_g,
                             const float* __restrict__ cdir_g)
{
    const int idx = blockIdx.x * blockDim.x + threadIdx.x;
    if (idx >= NWORK) return;
    const int v    = idx / NPAIRS;
    const int pair = idx - v * NPAIRS;
    const int ib   = pair * 2;

    const float sx  = src_g [2*v+0], sy  = src_g [2*v+1];
    const float dcx = detc_g[2*v+0], dcy = detc_g[2*v+1];
    const float ux  = u_g  [2*v+0], uy  = u_g  [2*v+1];
    const float nx  = -uy,          ny  = ux;
    const float cx  = center_g[0],  cy  = center_g[1];
    const float colx = cdir_g[0],   coly = cdir_g[1];
    const float rowx = -coly,       rowy = colx;

    const float vzx = cx - 0.5f*(R_-1)*DR_*rowx - 0.5f*(C_-1)*DC_*colx;
    const float vzy = cy - 0.5f*(R_-1)*DR_*rowy - 0.5f*(C_-1)*DC_*coly;

    const float src_d = sx*nx + sy*ny;
    const float su    = sx*ux + sy*uy;
    const float K     = (dcx*nx + dcy*ny) - src_d;
    const float h     = 0.5f*(NCOLS_-1)*DSPACE_;
    const float dzx   = dcx - h*ux, dzy = dcy - h*uy;
    const float A     = su - (dzx*ux + dzy*uy);

    const float bn0 = vzx*nx + vzy*ny - src_d;
    const float dnr = DR_*(rowx*nx + rowy*ny);
    const float dnc = DC_*(colx*nx + coly*ny);
    const float bu0 = vzx*ux + vzy*uy - su;
    const float dur = DR_*(rowx*ux + rowy*uy);
    const float duc = DC_*(colx*ux + coly*uy);

    const float den_c = bn0 + 0.5f*(R_-1)*dnr + 0.5f*(C_-1)*dnc;
    const float sig   = (den_c > 0.0f) ? 1.0f : -1.0f;
    const bool  tok   = (sig * K) > 0.0f;

    const float E  = A - (float)ib * DSPACE_;
    const float q0 = sig * (E*bn0 + K*bu0);
    const float qr = sig * (E*dnr + K*dur);
    const float qc = sig * (E*dnc + K*duc);
    const float b0 = sig * DSPACE_ * bn0;
    const float br = sig * DSPACE_ * dnr;
    const float bc = sig * DSPACE_ * dnc;

    const float ic_f = (float)ib + 0.5f;
    const float bxp = dzx + ic_f*DSPACE_*ux - sx;
    const float byp = dzy + ic_f*DSPACE_*uy - sy;
    const float dc_comp = bxp*colx + byp*coly;
    const float dr_comp = bxp*rowx + byp*rowy;
    const bool  drive_c = fabsf(dc_comp) >= fabsf(dr_comp);

    const float qs = drive_c ? qc : qr;
    const float qp = drive_c ? qr : qc;
    const float bs = drive_c ? bc : br;
    const float bp = drive_c ? br : bc;

    // pair wedge lines: Q + B = 0 (col = ib-1), Q - 2B = 0 (col = ib+2)
    const float gm  = qp + bp;
    const float gp2 = qp - 2.0f*bp;
    const float am  = __fdividef(-(q0 + b0),      gm);
    const float bm  = __fdividef(-(qs + bs),      gm);
    const float ap  = __fdividef(-(q0 - 2.0f*b0), gp2);
    const float bp3 = __fdividef(-(qs - 2.0f*bs), gp2);
    float alo, blo, ahi, bhi;
    if (fmaf(191.5f, bm, am) <= fmaf(191.5f, bp3, ap)) {
        alo = am; blo = bm; ahi = ap; bhi = bp3;
    } else {
        alo = ap; blo = bp3; ahi = am; bhi = bm;
    }

    int w0i, w1i;
    if (tok) drive_window(ahi, bhi, alo, blo, w0i, w1i);
    else     { w0i = 1; w1i = 0; }

    // BUGFIX (R14): drive_window may return w1i < 0; canonicalize every
    // empty window to (1, 0) so both fields are non-negative 16-bit values.
    if (w1i < w0i) { w0i = 1; w1i = 0; }

    const int packed = w1i | (drive_c ? (1 << 16) : 0);

    float4* o = g_pre + idx * 3;
    o[0] = make_float4(q0, qs, qp, b0);
    o[1] = make_float4(bs, bp, alo - 0.01f, blo);     // margin baked
    o[2] = make_float4(ahi + 0.01f, bhi,              // margin baked
                       __int_as_float(w0i), __int_as_float(packed));
}

// Walk driving coordinate s (lanes strided by 32), perp coord p with
// compile-time stride PSTR; SROW is the complementary stride.
template<int PSTR, int SROW>
__device__ __forceinline__ void walk(const float* __restrict__ img,
                                     int lane, int w0i, int w1i,
                                     float q0, float qs, float qp,
                                     float b0, float bs, float bp,
                                     float alo_m, float blo,
                                     float ahi_m, float bhi,
                                     float& acc0, float& acc1)
{
    const float* srow = img + (w0i + lane) * SROW;   // advances by 32*SROW
    for (int s = w0i + lane; s <= w1i; s += 32, srow += 32 * SROW) {
        const float sf  = (float)s;
        const float plo = fmaxf(fmaf(sf, blo, alo_m), 0.0f);
        const float phi = fminf(fmaf(sf, bhi, ahi_m), 383.0f);
        const int p0 = __float2int_ru(plo);
        const int n  = __float2int_rd(phi) - p0;
        if (n >= 0) {
            const float pf0 = (float)p0;
            const float Qb  = fmaf(pf0, qp, fmaf(sf, qs, q0));
            const float Bb  = fmaf(pf0, bp, fmaf(sf, bs, b0));
            const float* p  = srow + p0 * PSTR;
            #pragma unroll
            for (int k = 0; k < 5; ++k) {
                if (k <= n) {
                    const float Qp = fmaf((float)k, qp, Qb);
                    const float Bp = fmaf((float)k, bp, Bb);
                    const float rb = __fdividef(1.0f, Bp);
                    const float val = __ldg(p + k*PSTR);
                    const float wA = fmaf(-fabsf(Qp), rb, 1.0f);
                    const float wB = fmaf(-fabsf(Qp - Bp), rb, 1.0f);
                    acc0 = fmaf(fmaxf(wA, 0.0f), val, acc0);
                    acc1 = fmaf(fmaxf(wB, 0.0f), val, acc1);
                }
            }
            for (int k = 5; k <= n; ++k) {          // cold tail (safety)
                const float Qp = fmaf((float)k, qp, Qb);
                const float Bp = fmaf((float)k, bp, Bb);
                const float rb = __fdividef(1.0f, Bp);
                const float val = __ldg(p + k*PSTR);
                const float wA = fmaf(-fabsf(Qp), rb, 1.0f);
                const float wB = fmaf(-fabsf(Qp - Bp), rb, 1.0f);
                acc0 = fmaf(fmaxf(wA, 0.0f), val, acc0);
                acc1 = fmaf(fmaxf(wB, 0.0f), val, acc1);
            }
        }
    }
}

__global__ __launch_bounds__(32 * WARPS_PER_BLOCK, 12)
void fanbeam_fp_kernel(const float* __restrict__ img,
                       float* __restrict__ sino)
{
    const int v    = blockIdx.y;
    const int warp = threadIdx.x >> 5;
    const int lane = threadIdx.x & 31;
    const int pair = blockIdx.x * WARPS_PER_BLOCK + warp;   // adjacent pairs
    const int ib   = pair * 2;

    const float4* pp = g_pre + (v * NPAIRS + pair) * 3;
    const float4 A0 = __ldg(pp + 0);
    const float4 A1 = __ldg(pp + 1);
    const float4 A2 = __ldg(pp + 2);

    const float q0 = A0.x, qs = A0.y, qp = A0.z, b0 = A0.w;
    const float bs = A1.x, bp = A1.y, alo_m = A1.z, blo = A1.w;
    const float ahi_m = A2.x, bhi = A2.y;
    const int   w0i    = __float_as_int(A2.z);
    const int   packed = __float_as_int(A2.w);
    const int   w1i    = packed & 0xFFFF;
    const bool  drive_c = (packed >> 16) != 0;

    float acc0 = 0.0f, acc1 = 0.0f;

    if (w0i <= w1i) {
        if (drive_c)
            walk<C_, 1>(img, lane, w0i, w1i, q0, qs, qp, b0, bs, bp,
                        alo_m, blo, ahi_m, bhi, acc0, acc1);
        else
            walk<1, C_>(img, lane, w0i, w1i, q0, qs, qp, b0, bs, bp,
                        alo_m, blo, ahi_m, bhi, acc0, acc1);
    }

    #pragma unroll
    for (int off = 16; off > 0; off >>= 1) {
        acc0 += __shfl_xor_sync(0xffffffffu, acc0, off);
        acc1 += __shfl_xor_sync(0xffffffffu, acc1, off);
    }

    if (lane == 0) {
        sino[v*NCOLS_ + ib]     = acc0;
        sino[v*NCOLS_ + ib + 1] = acc1;
    }
}

extern "C" void kernel_launch(void* const* d_in, const int* in_sizes, int n_in,
                              void* d_out, int out_size)
{
    const float* img    = (const float*)d_in[0];
    const float* src    = (const float*)d_in[1];
    const float* detc   = (const float*)d_in[2];
    const float* u      = (const float*)d_in[3];
    const float* center = (const float*)d_in[4];
    const float* cdir   = (const float*)d_in[5];
    float* sino = (float*)d_out;

    setup_kernel<<<(NWORK + 255) / 256, 256>>>(src, detc, u, center, cdir);

    dim3 grid(NPAIRS / WARPS_PER_BLOCK, V_);
    dim3 block(32 * WARPS_PER_BLOCK);
    fanbeam_fp_kernel<<<grid, block>>>(img, sino);
}